// round 8
// baseline (speedup 1.0000x reference)
#include <cuda_runtime.h>
#include <cstdint>

// Unfold (im2col): x[32,64,64,64] f32, 3x3/s1 -> out[32,576,3844] f32
// out[(bc*9+3ki+kj)][l+e] = ch[ki*64 + kj + (l+e) + 2*floor((l+e)/62)]
//
// R6 core (padded-smem gather, 8 LDS + 6 SEL + 3 STG.128 per (m,ki)) plus:
// block owns 2 channels, both staged up-front via 4-byte cp.async into a
// double-buffered pitch-33-padded smem (4B cp.async lets the destination be
// the padded word address -> conflict-free gather preserved, zero regs,
// async). Channel 1's stage latency hides behind channel 0's compute, so
// the store stream never starves during staging.

#define HW    64
#define CH    4096
#define WO    62
#define L     3844
#define NV4   961             // float4 per output row
#define SMW   4240            // 4096 + pad + slack for C+7 overread

__device__ __forceinline__ int PADI(int w) { return w + (w >> 5); }

__device__ __forceinline__ uint32_t smem_u32(const void* p) {
    uint32_t a;
    asm("{ .reg .u64 t; cvta.to.shared.u64 t, %1; cvt.u32.u64 %0, t; }"
        : "=r"(a) : "l"(p));
    return a;
}

// R6 compute body: emit the 9 output rows of one channel from padded smem.
__device__ __forceinline__ void emit_channel(const float* __restrict__ sm,
                                             float4* __restrict__ dst4,
                                             int tid)
{
#pragma unroll
    for (int it = 0; it < 4; ++it) {             // 961 = 3*256 + 193
        const int m = tid + 256 * it;
        if (m < NV4) {
            const int l   = 4 * m;
            const int i0  = l / WO;              // const divisor -> mulhi
            const int j0  = l - WO * i0;
            const int b0  = l + 2 * i0;
            const bool cr = (j0 == 60);          // only e=2,3 cross (+2 words)

#pragma unroll
            for (int ki = 0; ki < 3; ++ki) {
                const int C = ki * HW + b0;

                const float s0 = sm[PADI(C + 0)];
                const float s1 = sm[PADI(C + 1)];
                const float s2 = sm[PADI(C + 2)];
                const float s3 = sm[PADI(C + 3)];
                const float s4 = sm[PADI(C + 4)];
                const float s5 = sm[PADI(C + 5)];
                const float s6 = sm[PADI(C + 6)];
                const float s7 = sm[PADI(C + 7)];

                float4 v;
                v.x = s0; v.y = s1;
                v.z = cr ? s4 : s2; v.w = cr ? s5 : s3;
                dst4[(3 * ki + 0) * NV4 + m] = v;
                v.x = s1; v.y = s2;
                v.z = cr ? s5 : s3; v.w = cr ? s6 : s4;
                dst4[(3 * ki + 1) * NV4 + m] = v;
                v.x = s2; v.y = s3;
                v.z = cr ? s6 : s4; v.w = cr ? s7 : s5;
                dst4[(3 * ki + 2) * NV4 + m] = v;
            }
        }
    }
}

__global__ __launch_bounds__(256, 5)
void unfold_kernel(const float* __restrict__ x, float* __restrict__ out)
{
    __shared__ float smbuf[2][SMW];

    const int tid = threadIdx.x;
    const int ch0 = 2 * blockIdx.x;              // channels ch0, ch0+1

    // ---- stage both channels via 4-byte cp.async into padded smem ----
#pragma unroll
    for (int p = 0; p < 2; ++p) {
        const float* __restrict__ src = x + (size_t)(ch0 + p) * CH;
        const uint32_t dbase = smem_u32(smbuf[p]);
#pragma unroll
        for (int k = 0; k < CH / 256; ++k) {     // 16 words per thread
            const int w = tid + 256 * k;         // lane-consecutive: coalesced
            const uint32_t d = dbase + 4u * (uint32_t)PADI(w);
            asm volatile("cp.async.ca.shared.global [%0], [%1], 4;"
                         :: "r"(d), "l"(src + w) : "memory");
        }
        asm volatile("cp.async.commit_group;" ::: "memory");
    }

    // ---- channel 0: wait for its group (ch1 still in flight), compute ----
    asm volatile("cp.async.wait_group 1;" ::: "memory");
    __syncthreads();
    emit_channel(smbuf[0],
                 reinterpret_cast<float4*>(out) + (size_t)ch0 * 9 * NV4, tid);

    // ---- channel 1 ----
    asm volatile("cp.async.wait_group 0;" ::: "memory");
    __syncthreads();
    emit_channel(smbuf[1],
                 reinterpret_cast<float4*>(out) + (size_t)(ch0 + 1) * 9 * NV4, tid);
}

extern "C" void kernel_launch(void* const* d_in, const int* in_sizes, int n_in,
                              void* d_out, int out_size)
{
    const float* x = (const float*)d_in[0];
    float* out = (float*)d_out;

    unfold_kernel<<<1024, 256>>>(x, out);        // 2 channels per block
}

// round 9
// speedup vs baseline: 1.5105x; 1.5105x over previous
#include <cuda_runtime.h>
#include <cstdint>

// Unfold (im2col): x[32,64,64,64] f32, 3x3/s1 -> out[32,576,3844] f32
// out[(bc*9+3ki+kj)][l+e] = ch[ki*64 + kj + (l+e) + 2*floor((l+e)/62)]
//
// R6 core: block = one channel staged in pitch-33 padded smem (conflict-free
// stride-4 gather). Per (m,ki) the 12 elements (kj=0..2, e=0..3) come from
// the 8-word window C..C+7; row-crossing folds in via 6 SELs.
// 8 LDS + 6 SEL + 3 STG.128 per (m,ki)  (~0.24 L1 wf/float4, near the floor).
// R9 deltas: st.global.cs streaming stores (no-reuse write stream; keep L2
// for eviction batching, not retention) + launch_bounds(256,6) for 6 CTAs/SM.

#define HW    64
#define CH    4096
#define WO    62
#define L     3844
#define NV4   961             // float4 per output row
#define SMW   4240            // 4096 + pad + slack for C+7 overread

__device__ __forceinline__ int PADI(int w) { return w + (w >> 5); }

__device__ __forceinline__ void stcs4(float4* p, float4 v) {
    asm volatile("st.global.cs.v4.f32 [%0], {%1,%2,%3,%4};"
                 :: "l"(p), "f"(v.x), "f"(v.y), "f"(v.z), "f"(v.w)
                 : "memory");
}

__global__ __launch_bounds__(256, 6)
void unfold_kernel(const float* __restrict__ x, float* __restrict__ out)
{
    __shared__ float sm[SMW];

    const int bc  = blockIdx.x;               // 0..2047
    const int tid = threadIdx.x;

    // ---- stage channel into padded smem (4 LDG.128 / thread) ----
    {
        const float4* __restrict__ s4 =
            reinterpret_cast<const float4*>(x + (size_t)bc * CH);
#pragma unroll
        for (int v = tid; v < CH / 4; v += 256) {
            float4 d = s4[v];
            int w = 4 * v;
            sm[PADI(w + 0)] = d.x;
            sm[PADI(w + 1)] = d.y;
            sm[PADI(w + 2)] = d.z;
            sm[PADI(w + 3)] = d.w;
        }
    }
    __syncthreads();

    float4* __restrict__ dst4 =
        reinterpret_cast<float4*>(out + (size_t)bc * 9 * L);

    // 961 = 3*256 + 193
#pragma unroll
    for (int it = 0; it < 4; ++it) {
        const int m = tid + 256 * it;
        if (m < NV4) {
            const int l   = 4 * m;
            const int i0  = l / WO;           // const divisor -> mulhi
            const int j0  = l - WO * i0;
            const int b0  = l + 2 * i0;
            const bool cr = (j0 == 60);       // only e=2,3 cross (+2 words)

#pragma unroll
            for (int ki = 0; ki < 3; ++ki) {
                const int C = ki * HW + b0;

                const float s0 = sm[PADI(C + 0)];
                const float s1 = sm[PADI(C + 1)];
                const float s2 = sm[PADI(C + 2)];
                const float s3 = sm[PADI(C + 3)];
                const float s4 = sm[PADI(C + 4)];
                const float s5 = sm[PADI(C + 5)];
                const float s6 = sm[PADI(C + 6)];
                const float s7 = sm[PADI(C + 7)];

                float4 v;
                // kj = 0
                v.x = s0; v.y = s1;
                v.z = cr ? s4 : s2; v.w = cr ? s5 : s3;
                stcs4(&dst4[(3 * ki + 0) * NV4 + m], v);
                // kj = 1
                v.x = s1; v.y = s2;
                v.z = cr ? s5 : s3; v.w = cr ? s6 : s4;
                stcs4(&dst4[(3 * ki + 1) * NV4 + m], v);
                // kj = 2
                v.x = s2; v.y = s3;
                v.z = cr ? s6 : s4; v.w = cr ? s7 : s5;
                stcs4(&dst4[(3 * ki + 2) * NV4 + m], v);
            }
        }
    }
}

extern "C" void kernel_launch(void* const* d_in, const int* in_sizes, int n_in,
                              void* d_out, int out_size)
{
    const float* x = (const float*)d_in[0];
    float* out = (float*)d_out;

    unfold_kernel<<<2048, 256>>>(x, out);     // one block per (b,c) channel
}

// round 10
// speedup vs baseline: 1.6094x; 1.0654x over previous
#include <cuda_runtime.h>
#include <cstdint>

// Unfold (im2col): x[32,64,64,64] f32, 3x3/s1 -> out[32,576,3844] f32
// out[(bc*9+3ki+kj)][l+e] = ch[ki*64 + kj + (l+e) + 2*floor((l+e)/62)]
//
// R9 core (padded-smem conflict-free gather; per (m,ki) the 12 elements
// come from the 8-word window C..C+7, row-crossing folded via 6 SELs;
// 8 LDS + 6 SEL + 3 st.global.cs.v4 per (m,ki)).
// R10 delta: 512-thread blocks -> half as many stage/sync prologues per SM,
// 2-deep m-loop, ~75% occupancy, smoother store stream.

#define HW    64
#define CH    4096
#define WO    62
#define L     3844
#define NV4   961             // float4 per output row
#define SMW   4240            // 4096 + pad + slack for C+7 overread
#define NT    512

__device__ __forceinline__ int PADI(int w) { return w + (w >> 5); }

__device__ __forceinline__ void stcs4(float4* p, float4 v) {
    asm volatile("st.global.cs.v4.f32 [%0], {%1,%2,%3,%4};"
                 :: "l"(p), "f"(v.x), "f"(v.y), "f"(v.z), "f"(v.w)
                 : "memory");
}

__global__ __launch_bounds__(NT)
void unfold_kernel(const float* __restrict__ x, float* __restrict__ out)
{
    __shared__ float sm[SMW];

    const int bc  = blockIdx.x;               // 0..2047
    const int tid = threadIdx.x;

    // ---- stage channel into padded smem (2 LDG.128 / thread) ----
    {
        const float4* __restrict__ s4 =
            reinterpret_cast<const float4*>(x + (size_t)bc * CH);
#pragma unroll
        for (int v = tid; v < CH / 4; v += NT) {
            float4 d = s4[v];
            int w = 4 * v;
            sm[PADI(w + 0)] = d.x;
            sm[PADI(w + 1)] = d.y;
            sm[PADI(w + 2)] = d.z;
            sm[PADI(w + 3)] = d.w;
        }
    }
    __syncthreads();

    float4* __restrict__ dst4 =
        reinterpret_cast<float4*>(out + (size_t)bc * 9 * L);

    // 961 = 512 + 449
#pragma unroll
    for (int it = 0; it < 2; ++it) {
        const int m = tid + NT * it;
        if (m < NV4) {
            const int l   = 4 * m;
            const int i0  = l / WO;           // const divisor -> mulhi
            const int j0  = l - WO * i0;
            const int b0  = l + 2 * i0;
            const bool cr = (j0 == 60);       // only e=2,3 cross (+2 words)

#pragma unroll
            for (int ki = 0; ki < 3; ++ki) {
                const int C = ki * HW + b0;

                const float s0 = sm[PADI(C + 0)];
                const float s1 = sm[PADI(C + 1)];
                const float s2 = sm[PADI(C + 2)];
                const float s3 = sm[PADI(C + 3)];
                const float s4 = sm[PADI(C + 4)];
                const float s5 = sm[PADI(C + 5)];
                const float s6 = sm[PADI(C + 6)];
                const float s7 = sm[PADI(C + 7)];

                float4 v;
                // kj = 0
                v.x = s0; v.y = s1;
                v.z = cr ? s4 : s2; v.w = cr ? s5 : s3;
                stcs4(&dst4[(3 * ki + 0) * NV4 + m], v);
                // kj = 1
                v.x = s1; v.y = s2;
                v.z = cr ? s5 : s3; v.w = cr ? s6 : s4;
                stcs4(&dst4[(3 * ki + 1) * NV4 + m], v);
                // kj = 2
                v.x = s2; v.y = s3;
                v.z = cr ? s6 : s4; v.w = cr ? s7 : s5;
                stcs4(&dst4[(3 * ki + 2) * NV4 + m], v);
            }
        }
    }
}

extern "C" void kernel_launch(void* const* d_in, const int* in_sizes, int n_in,
                              void* d_out, int out_size)
{
    const float* x = (const float*)d_in[0];
    float* out = (float*)d_out;

    unfold_kernel<<<2048, NT>>>(x, out);      // one block per (b,c) channel
}